// round 12
// baseline (speedup 1.0000x reference)
#include <cuda_runtime.h>
#include <cuda_fp16.h>

#define N_NODES 50000
#define N_EDGES 1600000
#define NB 10                // 128-edge batches per CTA (grid = 1250)

// Per-node precomputed readout vectors (one 128B line per node).
__device__ __align__(128) float g_prep[N_NODES * 32];
// L1 k8 frags: 8 frags x 32 lanes (uint = half2)
__device__ __align__(16) unsigned g_wfrags1[256];
// L2/L3/L4 k16 frags packed as nt-pairs: 36 qfrags x 32 lanes x uint4
__device__ __align__(16) uint4 g_wfragsq[1152];

// ---- SMEM layout (4-byte word offsets) ----
#define WF1_OFF 0            // 256 words
#define WFQ_OFF 256          // 1152 uint4 = 4608 words
#define CS_OFF  4864         // 16 rows x 132 floats
#define CS_STR  132          // 132 mod 32 == 4 -> conflict-free tail reads
#define SMEM_WORDS (CS_OFF + 16 * CS_STR)
#define SMEM_BYTES (SMEM_WORDS * 4)   // 27904 B

// qfrag bases: L2 = 0..15, L3 = 16..31, L4 = 32..35
#define QB_L2 0
#define QB_L3 16
#define QB_L4 32

__device__ __forceinline__ unsigned h2bits(__half2 h) { return *(unsigned*)&h; }

// silu via HW tanh, fully fp16x2: silu(x) = h + h*tanh(h), h = x/2.
__device__ __forceinline__ unsigned silu_h2(float x0, float x1) {
    __half2 h = __floats2half2_rn(x0, x1);
    __half2 hh = __hmul2(h, __floats2half2_rn(0.5f, 0.5f));
    unsigned t;
    asm("tanh.approx.f16x2 %0, %1;" : "=r"(t) : "r"(h2bits(hh)));
    __half2 r = __hfma2(hh, *(__half2*)&t, hh);
    return h2bits(r);
}

__device__ __forceinline__ void mma_f16(float* d, unsigned a0, unsigned a1,
                                        unsigned a2, unsigned a3,
                                        unsigned b0, unsigned b1) {
    asm volatile(
        "mma.sync.aligned.m16n8k16.row.col.f32.f16.f16.f32 "
        "{%0,%1,%2,%3}, {%4,%5,%6,%7}, {%8,%9}, {%0,%1,%2,%3};"
        : "+f"(d[0]), "+f"(d[1]), "+f"(d[2]), "+f"(d[3])
        : "r"(a0), "r"(a1), "r"(a2), "r"(a3), "r"(b0), "r"(b1));
}

__device__ __forceinline__ void mma_f16_k8(float* d, unsigned a0, unsigned a1, unsigned b0) {
    asm volatile(
        "mma.sync.aligned.m16n8k8.row.col.f32.f16.f16.f32 "
        "{%0,%1,%2,%3}, {%4,%5}, {%6}, {%0,%1,%2,%3};"
        : "+f"(d[0]), "+f"(d[1]), "+f"(d[2]), "+f"(d[3])
        : "r"(a0), "r"(a1), "r"(b0));
}

__device__ __forceinline__ void red1(float* a, float v) {
    asm volatile("red.global.add.f32 [%0], %1;" :: "l"(a), "f"(v) : "memory");
}

// ============================================================================
// Setup kernel: weight frag packing (low blocks) + per-node prep + out zero.
// ============================================================================
__global__ void __launch_bounds__(256)
setup_kernel(const float* __restrict__ nf,   // node_feats [N,256]
             const float* __restrict__ W0,   // [8,64]
             const float* __restrict__ W1,   // [8,64]
             const float* __restrict__ w1, const float* __restrict__ w2,
             const float* __restrict__ w3, const float* __restrict__ w4,
             float* __restrict__ out)
{
    const int tid = threadIdx.x;
    const float s8 = 0.3535533905932738f, s64 = 0.125f;

    int idx = blockIdx.x * 256 + tid;
    if (idx < 256) {
        // L1 k8 frags
        int f = idx >> 5, lane = idx & 31;
        int c = lane & 3, g = lane >> 2;
        int n = f * 8 + g;
        __half2 p = __floats2half2_rn(w1[(2*c) * 64 + n] * s8,
                                      w1[(2*c + 1) * 64 + n] * s8);
        g_wfrags1[idx] = h2bits(p);
    } else if (idx < 256 + 1152) {
        // k16 qfrags: {frag(nt0).x,.y, frag(nt1).x,.y}
        int t = idx - 256;
        int qf = t >> 5, lane = t & 31;
        int c = lane & 3, g = lane >> 2;
        const float* w; int ncols, kt, nt0;
        if (qf < 16)      { w = w2; ncols = 64; kt = qf >> 2;        nt0 = (qf & 3) * 2; }
        else if (qf < 32) { w = w3; ncols = 64; kt = (qf - 16) >> 2; nt0 = ((qf - 16) & 3) * 2; }
        else              { w = w4; ncols = 16; kt = qf - 32;        nt0 = 0; }
        int kb = kt * 16 + 2 * c;
        int n0 = nt0 * 8 + g, n1 = (nt0 + 1) * 8 + g;
        __half2 x0 = __floats2half2_rn(w[kb * ncols + n0] * s64, w[(kb + 1) * ncols + n0] * s64);
        __half2 y0 = __floats2half2_rn(w[(kb + 8) * ncols + n0] * s64, w[(kb + 9) * ncols + n0] * s64);
        __half2 x1 = __floats2half2_rn(w[kb * ncols + n1] * s64, w[(kb + 1) * ncols + n1] * s64);
        __half2 y1 = __floats2half2_rn(w[(kb + 8) * ncols + n1] * s64, w[(kb + 9) * ncols + n1] * s64);
        g_wfragsq[t] = make_uint4(h2bits(x0), h2bits(y0), h2bits(x1), h2bits(y1));
    }

    // ---- per-node prep (warp per node) ----
    __shared__ float sW0[512], sW1[512];
    for (int i = tid; i < 512; i += 256) { sW0[i] = W0[i]; sW1[i] = W1[i]; }
    __syncthreads();

    const int warp = tid >> 5;
    const int lane = tid & 31;
    const int n = blockIdx.x * 8 + warp;
    if (n >= N_NODES) return;

    const float* nrow = nf + (size_t)n * 256;
    const int v1 = lane, v2 = lane + 32;
    float x1 = nrow[v1], x2 = nrow[v2];
    float y1[3], y2[3];
    #pragma unroll
    for (int k = 0; k < 3; k++) {
        y1[k] = nrow[64 + v1 * 3 + k];
        y2[k] = nrow[64 + v2 * 3 + k];
    }

    float P[32];
    #pragma unroll
    for (int u = 0; u < 8; u++)
        P[u] = fmaf(sW0[u * 64 + v1], x1, sW0[u * 64 + v2] * x2);
    #pragma unroll
    for (int u = 0; u < 8; u++) {
        float wa = sW1[u * 64 + v1], wb = sW1[u * 64 + v2];
        #pragma unroll
        for (int k = 0; k < 3; k++)
            P[8 + u * 3 + k] = fmaf(wa, y1[k], wb * y2[k]);
    }

    #pragma unroll
    for (int off = 16; off; off >>= 1) {
        #pragma unroll
        for (int j = 0; j < 32; j++)
            P[j] += __shfl_xor_sync(0xffffffffu, P[j], off);
    }

    if (lane == 0) {
        const float c0 = 0.03125f;                        // 1/sqrt(8*64*2)
        const float c1 = 0.03125f * 0.5773502691896258f;  // c/sqrt(3)
        float* dst = g_prep + (size_t)n * 32;
        #pragma unroll
        for (int j = 0; j < 8; j++)  dst[j] = P[j] * c0;
        #pragma unroll
        for (int j = 8; j < 32; j++) dst[j] = P[j] * c1;
        out[n] = 0.f;
    }
}

// ============================================================================
// Edge kernel: register-resident activation chain (D-frag == next A-frag).
// ============================================================================
__global__ void __launch_bounds__(256, 3)
edge_kernel(const float* __restrict__ ef,   // edge_feats [E,8]
            const float* __restrict__ ea,   // edge_attrs [E,4]
            const float* __restrict__ qi,   // charges_induced [N,8]
            const int*   __restrict__ eidx, // edge_index [2,E]
            float* __restrict__ out)
{
    extern __shared__ float smem[];
    unsigned* wf1 = (unsigned*)smem;
    uint4*    wfq = (uint4*)(smem + WFQ_OFF);
    float*    csm = smem + CS_OFF;

    const int tid  = threadIdx.x;
    const int lane = tid & 31;
    const int m0   = (tid >> 5) * 16;
    const int half = lane & 1;
    const int cm   = m0 + (lane >> 1);   // edge column for gather staging
    const int c    = lane & 3;
    const int g    = lane >> 2;

    // Weight frags -> SMEM (block-cooperative; the only block sync).
    {
        const float4* s1 = (const float4*)g_wfrags1;   // 64 float4
        float4* d1 = (float4*)smem;
        if (tid < 64) d1[tid] = s1[tid];
        const float4* s2 = (const float4*)g_wfragsq;   // 1152 float4
        float4* d2 = (float4*)(smem + WFQ_OFF);
        #pragma unroll
        for (int i = 0; i < 4; i++) d2[tid + i * 256] = s2[tid + i * 256];
        if (tid < 128) d2[tid + 1024] = s2[tid + 1024];
    }
    __syncthreads();

    const int ebase = blockIdx.x * (128 * NB);

    int s_n = eidx[ebase + cm];
    int r_n = eidx[N_EDGES + ebase + cm];

    float acc[8][4];
    #define ZACC(N) { _Pragma("unroll") for (int i = 0; i < N; i++) { \
        acc[i][0]=0.f; acc[i][1]=0.f; acc[i][2]=0.f; acc[i][3]=0.f; } }

    #pragma unroll 1
    for (int b = 0; b < NB; b++) {
        const int s_ = s_n;
        const int r_ = r_n;
        const int me = ebase + b * 128 + cm;
        const int e0 = ebase + b * 128 + m0;   // warp's first edge

        // ---- Parallel LDG round ----
        float4 at = *(const float4*)(ea + (size_t)me * 4);
        float2 fa = *(const float2*)(ef + (size_t)(e0 + g) * 8 + 2 * c);
        float2 fb = *(const float2*)(ef + (size_t)(e0 + g + 8) * 8 + 2 * c);
        float4 q0 = *(const float4*)(qi + (size_t)s_ * 8);
        float4 q1 = *(const float4*)(qi + (size_t)s_ * 8 + 4);
        const float4* pr = (const float4*)(g_prep + (size_t)r_ * 32);

        if (b + 1 < NB) {
            s_n = eidx[ebase + (b + 1) * 128 + cm];
            r_n = eidx[N_EDGES + ebase + (b + 1) * 128 + cm];
        }

        // Contract gather into csm[16][edge].
        float q[8] = {q0.x, q0.y, q0.z, q0.w, q1.x, q1.y, q1.z, q1.w};
        if (half == 0) {
            float4 Aa = pr[0], Ab = pr[1];
            float A0[8] = {Aa.x, Aa.y, Aa.z, Aa.w, Ab.x, Ab.y, Ab.z, Ab.w};
            #pragma unroll
            for (int u = 0; u < 8; u++) csm[u * CS_STR + cm] = (q[u] * at.x) * A0[u];
        } else {
            float A1[24];
            #pragma unroll
            for (int i = 0; i < 6; i++) {
                float4 v = pr[2 + i];
                A1[4*i] = v.x; A1[4*i+1] = v.y; A1[4*i+2] = v.z; A1[4*i+3] = v.w;
            }
            #pragma unroll
            for (int u = 0; u < 8; u++) {
                float bs = at.y * A1[3*u];
                bs = fmaf(at.z, A1[3*u + 1], bs);
                bs = fmaf(at.w, A1[3*u + 2], bs);
                csm[(8 + u) * CS_STR + cm] = q[u] * bs;
            }
        }
        __syncwarp();

        // ---- Layer 1: 8 -> 64 (k8; A direct from gmem, cvt to fp16) ----
        unsigned a0 = h2bits(__floats2half2_rn(fa.x, fa.y));
        unsigned a1 = h2bits(__floats2half2_rn(fb.x, fb.y));
        ZACC(8);
        #pragma unroll
        for (int nt = 0; nt < 8; nt++)
            mma_f16_k8(acc[nt], a0, a1, wf1[nt * 32 + lane]);

        unsigned hlo[8], hhi[8];
        #pragma unroll
        for (int nt = 0; nt < 8; nt++) {
            hlo[nt] = silu_h2(acc[nt][0], acc[nt][1]);
            hhi[nt] = silu_h2(acc[nt][2], acc[nt][3]);
        }

        // ---- Layer 2: 64 -> 64 (activations stay in registers) ----
        ZACC(8);
        #pragma unroll
        for (int kt = 0; kt < 4; kt++) {
            unsigned A0 = hlo[2*kt], A1 = hhi[2*kt];
            unsigned A2 = hlo[2*kt+1], A3 = hhi[2*kt+1];
            #pragma unroll
            for (int np = 0; np < 4; np++) {
                uint4 B = wfq[(QB_L2 + kt * 4 + np) * 32 + lane];
                mma_f16(acc[2*np],   A0, A1, A2, A3, B.x, B.y);
                mma_f16(acc[2*np+1], A0, A1, A2, A3, B.z, B.w);
            }
        }
        #pragma unroll
        for (int nt = 0; nt < 8; nt++) {
            hlo[nt] = silu_h2(acc[nt][0], acc[nt][1]);
            hhi[nt] = silu_h2(acc[nt][2], acc[nt][3]);
        }

        // ---- Layer 3: 64 -> 64 ----
        ZACC(8);
        #pragma unroll
        for (int kt = 0; kt < 4; kt++) {
            unsigned A0 = hlo[2*kt], A1 = hhi[2*kt];
            unsigned A2 = hlo[2*kt+1], A3 = hhi[2*kt+1];
            #pragma unroll
            for (int np = 0; np < 4; np++) {
                uint4 B = wfq[(QB_L3 + kt * 4 + np) * 32 + lane];
                mma_f16(acc[2*np],   A0, A1, A2, A3, B.x, B.y);
                mma_f16(acc[2*np+1], A0, A1, A2, A3, B.z, B.w);
            }
        }
        #pragma unroll
        for (int nt = 0; nt < 8; nt++) {
            hlo[nt] = silu_h2(acc[nt][0], acc[nt][1]);
            hhi[nt] = silu_h2(acc[nt][2], acc[nt][3]);
        }

        // ---- Layer 4: 64 -> 16 (no activation) ----
        ZACC(2);
        #pragma unroll
        for (int kt = 0; kt < 4; kt++) {
            unsigned A0 = hlo[2*kt], A1 = hhi[2*kt];
            unsigned A2 = hlo[2*kt+1], A3 = hhi[2*kt+1];
            uint4 B = wfq[(QB_L4 + kt) * 32 + lane];
            mma_f16(acc[0], A0, A1, A2, A3, B.x, B.y);
            mma_f16(acc[1], A0, A1, A2, A3, B.z, B.w);
        }

        // ---- Tail: dot(tp, C) in D-frag domain ----
        // acc[nt][0,1] = (edge g, outs nt*8+2c, +1); [2,3] = edge g+8.
        const float* cg  = csm + m0 + g;
        const float* cg8 = csm + m0 + g + 8;
        float sA = acc[0][0] * cg[(2*c)     * CS_STR]
                 + acc[0][1] * cg[(2*c + 1) * CS_STR]
                 + acc[1][0] * cg[(8 + 2*c) * CS_STR]
                 + acc[1][1] * cg[(9 + 2*c) * CS_STR];
        float sB = acc[0][2] * cg8[(2*c)     * CS_STR]
                 + acc[0][3] * cg8[(2*c + 1) * CS_STR]
                 + acc[1][2] * cg8[(8 + 2*c) * CS_STR]
                 + acc[1][3] * cg8[(9 + 2*c) * CS_STR];
        sA += __shfl_xor_sync(0xffffffffu, sA, 1);
        sA += __shfl_xor_sync(0xffffffffu, sA, 2);
        sB += __shfl_xor_sync(0xffffffffu, sB, 1);
        sB += __shfl_xor_sync(0xffffffffu, sB, 2);
        int rg  = __shfl_sync(0xffffffffu, r_, 2 * g);
        int rg8 = __shfl_sync(0xffffffffu, r_, 2 * g + 16);
        if (c == 0) {
            red1(out + rg,  sA);
            red1(out + rg8, sB);
        }
        __syncwarp();   // tail csm reads done before next batch overwrites
    }
}

extern "C" void kernel_launch(void* const* d_in, const int* in_sizes, int n_in,
                              void* d_out, int out_size)
{
    const float* node_feats      = (const float*)d_in[0];
    const float* charges_induced = (const float*)d_in[2];
    const float* edge_feats      = (const float*)d_in[3];
    const float* edge_attrs      = (const float*)d_in[4];
    const float* mlp_w1          = (const float*)d_in[6];
    const float* mlp_w2          = (const float*)d_in[7];
    const float* mlp_w3          = (const float*)d_in[8];
    const float* mlp_w4          = (const float*)d_in[9];
    const float* W0              = (const float*)d_in[10];
    const float* W1              = (const float*)d_in[11];
    const int*   eidx            = (const int*)d_in[12];
    float* out = (float*)d_out;

    setup_kernel<<<(N_NODES + 7) / 8, 256>>>(node_feats, W0, W1,
                                             mlp_w1, mlp_w2, mlp_w3, mlp_w4, out);

    cudaFuncSetAttribute(edge_kernel, cudaFuncAttributeMaxDynamicSharedMemorySize, SMEM_BYTES);
    edge_kernel<<<N_EDGES / (128 * NB), 256, SMEM_BYTES>>>(
        edge_feats, edge_attrs, charges_induced, eidx, out);
}

// round 13
// speedup vs baseline: 1.1898x; 1.1898x over previous
#include <cuda_runtime.h>
#include <cuda_fp16.h>

#define N_NODES 50000
#define N_EDGES 1600000
#define NB 20                // 128-edge batches per CTA (grid = 625)

// Per-node precomputed readout vectors (one 128B line per node).
__device__ __align__(128) float g_prep[N_NODES * 32];
// L1 k8 frags: 8 frags x 32 lanes (uint = half2)
__device__ __align__(16) unsigned g_wfrags1[256];
// L2/L3/L4 k16 frags: 72 frags x 32 lanes (uint2)
__device__ __align__(16) uint2 g_wfrags2[2304];

// ---- SMEM layout (4-byte word offsets) ----
#define H2S     136          // hp row stride; 136 mod 32 == 8 -> conflict-free
#define CS_STR  132          // csm row stride; 132 mod 32 == 4 -> conflict-free tail
#define WF1_OFF 0            // 256 words
#define WF2_OFF 256          // 4608 words
#define HP_OFF  4864         // 32 pair-rows x 136 = 4352 words
#define CS_OFF  9216         // 16 rows x 132 = 2112 words
#define SMEM_WORDS 11328
#define SMEM_BYTES (SMEM_WORDS * 4)   // 45312 B -> 4 CTAs/SM

// frag bases inside wf2 (units of frags = 32 uint2)
#define FB_L2 0
#define FB_L3 32
#define FB_L4 64

__device__ __forceinline__ unsigned h2bits(__half2 h) { return *(unsigned*)&h; }

// silu via HW tanh, fully fp16x2: silu(x) = h + h*tanh(h), h = x/2.
__device__ __forceinline__ unsigned silu_h2(float x0, float x1) {
    __half2 h = __floats2half2_rn(x0, x1);
    __half2 hh = __hmul2(h, __floats2half2_rn(0.5f, 0.5f));
    unsigned t;
    asm("tanh.approx.f16x2 %0, %1;" : "=r"(t) : "r"(h2bits(hh)));
    __half2 r = __hfma2(hh, *(__half2*)&t, hh);
    return h2bits(r);
}

__device__ __forceinline__ void mma_f16(float* d, unsigned a0, unsigned a1,
                                        unsigned a2, unsigned a3,
                                        unsigned b0, unsigned b1) {
    asm volatile(
        "mma.sync.aligned.m16n8k16.row.col.f32.f16.f16.f32 "
        "{%0,%1,%2,%3}, {%4,%5,%6,%7}, {%8,%9}, {%0,%1,%2,%3};"
        : "+f"(d[0]), "+f"(d[1]), "+f"(d[2]), "+f"(d[3])
        : "r"(a0), "r"(a1), "r"(a2), "r"(a3), "r"(b0), "r"(b1));
}

__device__ __forceinline__ void mma_f16_k8(float* d, unsigned a0, unsigned a1, unsigned b0) {
    asm volatile(
        "mma.sync.aligned.m16n8k8.row.col.f32.f16.f16.f32 "
        "{%0,%1,%2,%3}, {%4,%5}, {%6}, {%0,%1,%2,%3};"
        : "+f"(d[0]), "+f"(d[1]), "+f"(d[2]), "+f"(d[3])
        : "r"(a0), "r"(a1), "r"(b0));
}

__device__ __forceinline__ void red1(float* a, float v) {
    asm volatile("red.global.add.f32 [%0], %1;" :: "l"(a), "f"(v) : "memory");
}

// ============================================================================
// Setup kernel: weight frag packing (low blocks) + per-node prep + out zero.
// ============================================================================
__global__ void __launch_bounds__(256)
setup_kernel(const float* __restrict__ nf,   // node_feats [N,256]
             const float* __restrict__ W0,   // [8,64]
             const float* __restrict__ W1,   // [8,64]
             const float* __restrict__ w1, const float* __restrict__ w2,
             const float* __restrict__ w3, const float* __restrict__ w4,
             float* __restrict__ out)
{
    const int tid = threadIdx.x;
    const float s8 = 0.3535533905932738f, s64 = 0.125f;

    int idx = blockIdx.x * 256 + tid;
    if (idx < 256) {
        int f = idx >> 5, lane = idx & 31;
        int c = lane & 3, g = lane >> 2;
        int n = f * 8 + g;
        __half2 p = __floats2half2_rn(w1[(2*c) * 64 + n] * s8,
                                      w1[(2*c + 1) * 64 + n] * s8);
        g_wfrags1[idx] = h2bits(p);
    } else if (idx < 2560) {
        int t = idx - 256;
        int f = t >> 5, lane = t & 31;
        int c = lane & 3, g = lane >> 2;
        const float* w; int ncols, NT, fl;
        if (f < 32)      { w = w2; ncols = 64; NT = 8; fl = f; }
        else if (f < 64) { w = w3; ncols = 64; NT = 8; fl = f - 32; }
        else             { w = w4; ncols = 16; NT = 2; fl = f - 64; }
        int kt = fl / NT, nt = fl - kt * NT;
        int n = nt * 8 + g, kb = kt * 16 + 2 * c;
        __half2 x = __floats2half2_rn(w[kb * ncols + n] * s64,
                                      w[(kb + 1) * ncols + n] * s64);
        __half2 y = __floats2half2_rn(w[(kb + 8) * ncols + n] * s64,
                                      w[(kb + 9) * ncols + n] * s64);
        g_wfrags2[t] = make_uint2(h2bits(x), h2bits(y));
    }

    // ---- per-node prep (warp per node) ----
    __shared__ float sW0[512], sW1[512];
    for (int i = tid; i < 512; i += 256) { sW0[i] = W0[i]; sW1[i] = W1[i]; }
    __syncthreads();

    const int warp = tid >> 5;
    const int lane = tid & 31;
    const int n = blockIdx.x * 8 + warp;
    if (n >= N_NODES) return;

    const float* nrow = nf + (size_t)n * 256;
    const int v1 = lane, v2 = lane + 32;
    float x1 = nrow[v1], x2 = nrow[v2];
    float y1[3], y2[3];
    #pragma unroll
    for (int k = 0; k < 3; k++) {
        y1[k] = nrow[64 + v1 * 3 + k];
        y2[k] = nrow[64 + v2 * 3 + k];
    }

    float P[32];
    #pragma unroll
    for (int u = 0; u < 8; u++)
        P[u] = fmaf(sW0[u * 64 + v1], x1, sW0[u * 64 + v2] * x2);
    #pragma unroll
    for (int u = 0; u < 8; u++) {
        float wa = sW1[u * 64 + v1], wb = sW1[u * 64 + v2];
        #pragma unroll
        for (int k = 0; k < 3; k++)
            P[8 + u * 3 + k] = fmaf(wa, y1[k], wb * y2[k]);
    }

    #pragma unroll
    for (int off = 16; off; off >>= 1) {
        #pragma unroll
        for (int j = 0; j < 32; j++)
            P[j] += __shfl_xor_sync(0xffffffffu, P[j], off);
    }

    if (lane == 0) {
        const float c0 = 0.03125f;                        // 1/sqrt(8*64*2)
        const float c1 = 0.03125f * 0.5773502691896258f;  // c/sqrt(3)
        float* dst = g_prep + (size_t)n * 32;
        #pragma unroll
        for (int j = 0; j < 8; j++)  dst[j] = P[j] * c0;
        #pragma unroll
        for (int j = 8; j < 32; j++) dst[j] = P[j] * c1;
        out[n] = 0.f;
    }
}

// k16 layer: warp computes 16 edges x NT*8 outputs over KT*16 K.
template<int KT, int NT>
__device__ __forceinline__ void mma_layer(const uint2* __restrict__ wf,
                                          const unsigned* __restrict__ hp,
                                          int m0, int lane, float acc[][4]) {
    const int c = lane & 3, g = lane >> 2;
    #pragma unroll
    for (int kt = 0; kt < KT; kt++) {
        unsigned a0 = hp[(kt * 8 + c)     * H2S + m0 + g];
        unsigned a1 = hp[(kt * 8 + c)     * H2S + m0 + g + 8];
        unsigned a2 = hp[(kt * 8 + c + 4) * H2S + m0 + g];
        unsigned a3 = hp[(kt * 8 + c + 4) * H2S + m0 + g + 8];
        #pragma unroll
        for (int nt = 0; nt < NT; nt++) {
            uint2 b = wf[(kt * NT + nt) * 32 + lane];
            mma_f16(acc[nt], a0, a1, a2, a3, b.x, b.y);
        }
    }
}

// No lead syncwarp: mma.sync is warp-collective, so all lanes' hp reads for
// this layer completed before any lane reaches these stores.
template<int NT>
__device__ __forceinline__ void store_acts_h(unsigned* hp, int m0, int lane,
                                             float acc[][4]) {
    const int c = lane & 3, g = lane >> 2;
    #pragma unroll
    for (int nt = 0; nt < NT; nt++) {
        hp[(nt * 4 + c) * H2S + m0 + g]     = silu_h2(acc[nt][0], acc[nt][1]);
        hp[(nt * 4 + c) * H2S + m0 + g + 8] = silu_h2(acc[nt][2], acc[nt][3]);
    }
    __syncwarp();   // stores visible before next layer's loads
}

__global__ void __launch_bounds__(256, 4)
edge_kernel(const float* __restrict__ ef,   // edge_feats [E,8]
            const float* __restrict__ ea,   // edge_attrs [E,4]
            const float* __restrict__ qi,   // charges_induced [N,8]
            const int*   __restrict__ eidx, // edge_index [2,E]
            float* __restrict__ out)
{
    extern __shared__ float smem[];
    unsigned* wf1 = (unsigned*)smem;
    uint2*    wf2 = (uint2*)(smem + WF2_OFF);
    unsigned* hp  = (unsigned*)(smem + HP_OFF);
    float*    csm = smem + CS_OFF;

    const int tid  = threadIdx.x;
    const int lane = tid & 31;
    const int m0   = (tid >> 5) * 16;
    const int half = lane & 1;
    const int cm   = m0 + (lane >> 1);   // this lane's edge column
    const int c    = lane & 3;
    const int g    = lane >> 2;

    // Weight frags -> SMEM (block-cooperative; the only block sync).
    {
        const float4* s1 = (const float4*)g_wfrags1;   // 64 float4
        float4* d1 = (float4*)smem;
        if (tid < 64) d1[tid] = s1[tid];
        const float4* s2 = (const float4*)g_wfrags2;   // 1152 float4
        float4* d2 = (float4*)(smem + WF2_OFF);
        #pragma unroll
        for (int i = 0; i < 4; i++) d2[tid + i * 256] = s2[tid + i * 256];
        if (tid < 128) d2[tid + 1024] = s2[tid + 1024];
    }
    __syncthreads();

    const int ebase = blockIdx.x * (128 * NB);

    // Prefetch batch 0's indices (breaks the eidx -> qi/prep chain).
    int s_n = eidx[ebase + cm];
    int r_n = eidx[N_EDGES + ebase + cm];

    float acc[8][4];
    #define ZACC(N) { _Pragma("unroll") for (int i = 0; i < N; i++) { \
        acc[i][0]=0.f; acc[i][1]=0.f; acc[i][2]=0.f; acc[i][3]=0.f; } }

    #pragma unroll 1
    for (int b = 0; b < NB; b++) {
        const int s_ = s_n;
        const int r_ = r_n;
        const int me = ebase + b * 128 + cm;

        // ---- Single parallel LDG round ----
        float4 at = *(const float4*)(ea + (size_t)me * 4);
        float4 f4 = *(const float4*)(ef + (size_t)me * 8 + half * 4);
        float4 q0 = *(const float4*)(qi + (size_t)s_ * 8);
        float4 q1 = *(const float4*)(qi + (size_t)s_ * 8 + 4);
        const float4* pr = (const float4*)(g_prep + (size_t)r_ * 32);

        // Prefetch next batch's indices.
        if (b + 1 < NB) {
            s_n = eidx[ebase + (b + 1) * 128 + cm];
            r_n = eidx[N_EDGES + ebase + (b + 1) * 128 + cm];
        }

        // Stage layer-1 inputs (hp pair-rows 0..3).
        hp[(2 * half)     * H2S + cm] = h2bits(__floats2half2_rn(f4.x, f4.y));
        hp[(2 * half + 1) * H2S + cm] = h2bits(__floats2half2_rn(f4.z, f4.w));

        // Contract gather into csm[16][edge] (stride 132).
        float q[8] = {q0.x, q0.y, q0.z, q0.w, q1.x, q1.y, q1.z, q1.w};
        if (half == 0) {
            float4 Aa = pr[0], Ab = pr[1];
            float A0[8] = {Aa.x, Aa.y, Aa.z, Aa.w, Ab.x, Ab.y, Ab.z, Ab.w};
            #pragma unroll
            for (int u = 0; u < 8; u++) csm[u * CS_STR + cm] = (q[u] * at.x) * A0[u];
        } else {
            float A1[24];
            #pragma unroll
            for (int i = 0; i < 6; i++) {
                float4 v = pr[2 + i];
                A1[4*i] = v.x; A1[4*i+1] = v.y; A1[4*i+2] = v.z; A1[4*i+3] = v.w;
            }
            #pragma unroll
            for (int u = 0; u < 8; u++) {
                float bs = at.y * A1[3*u];
                bs = fmaf(at.z, A1[3*u + 1], bs);
                bs = fmaf(at.w, A1[3*u + 2], bs);
                csm[(8 + u) * CS_STR + cm] = q[u] * bs;
            }
        }
        __syncwarp();

        // ---- Layer 1: 8 -> 64 (k8) ----
        ZACC(8);
        {
            unsigned a0 = hp[c * H2S + m0 + g];
            unsigned a1 = hp[c * H2S + m0 + g + 8];
            #pragma unroll
            for (int nt = 0; nt < 8; nt++)
                mma_f16_k8(acc[nt], a0, a1, wf1[nt * 32 + lane]);
        }
        store_acts_h<8>(hp, m0, lane, acc);

        ZACC(8); mma_layer<4, 8>(wf2 + FB_L2 * 32, hp, m0, lane, acc);
        store_acts_h<8>(hp, m0, lane, acc);

        ZACC(8); mma_layer<4, 8>(wf2 + FB_L3 * 32, hp, m0, lane, acc);
        store_acts_h<8>(hp, m0, lane, acc);

        // ---- Layer 4: 64 -> 16, tail directly in D-fragment domain ----
        ZACC(2); mma_layer<4, 2>(wf2 + FB_L4 * 32, hp, m0, lane, acc);

        // Thread (g,c) holds tp rows {g, g+8} x cols {nt*8+2c, nt*8+2c+1}.
        const float* cg  = csm + m0 + g;
        const float* cg8 = csm + m0 + g + 8;
        float sA = acc[0][0] * cg[(2*c)     * CS_STR]
                 + acc[0][1] * cg[(2*c + 1) * CS_STR]
                 + acc[1][0] * cg[(8 + 2*c) * CS_STR]
                 + acc[1][1] * cg[(9 + 2*c) * CS_STR];
        float sB = acc[0][2] * cg8[(2*c)     * CS_STR]
                 + acc[0][3] * cg8[(2*c + 1) * CS_STR]
                 + acc[1][2] * cg8[(8 + 2*c) * CS_STR]
                 + acc[1][3] * cg8[(9 + 2*c) * CS_STR];
        sA += __shfl_xor_sync(0xffffffffu, sA, 1);
        sA += __shfl_xor_sync(0xffffffffu, sA, 2);
        sB += __shfl_xor_sync(0xffffffffu, sB, 1);
        sB += __shfl_xor_sync(0xffffffffu, sB, 2);
        int rg  = __shfl_sync(0xffffffffu, r_, 2 * g);
        int rg8 = __shfl_sync(0xffffffffu, r_, 2 * g + 16);
        if (c == 0) {
            red1(out + rg,  sA);
            red1(out + rg8, sB);
        }
        __syncwarp();   // tail csm reads done before next batch overwrites
    }
}

extern "C" void kernel_launch(void* const* d_in, const int* in_sizes, int n_in,
                              void* d_out, int out_size)
{
    const float* node_feats      = (const float*)d_in[0];
    const float* charges_induced = (const float*)d_in[2];
    const float* edge_feats      = (const float*)d_in[3];
    const float* edge_attrs      = (const float*)d_in[4];
    const float* mlp_w1          = (const float*)d_in[6];
    const float* mlp_w2          = (const float*)d_in[7];
    const float* mlp_w3          = (const float*)d_in[8];
    const float* mlp_w4          = (const float*)d_in[9];
    const float* W0              = (const float*)d_in[10];
    const float* W1              = (const float*)d_in[11];
    const int*   eidx            = (const int*)d_in[12];
    float* out = (float*)d_out;

    setup_kernel<<<(N_NODES + 7) / 8, 256>>>(node_feats, W0, W1,
                                             mlp_w1, mlp_w2, mlp_w3, mlp_w4, out);

    cudaFuncSetAttribute(edge_kernel, cudaFuncAttributeMaxDynamicSharedMemorySize, SMEM_BYTES);
    edge_kernel<<<N_EDGES / (128 * NB), 256, SMEM_BYTES>>>(
        edge_feats, edge_attrs, charges_induced, eidx, out);
}

// round 14
// speedup vs baseline: 1.3423x; 1.1282x over previous
#include <cuda_runtime.h>
#include <cuda_fp16.h>

#define N_NODES 50000
#define N_EDGES 1600000
#define NBATCH  12500        // total 128-edge batches
#define GRID    592          // 148 SMs x 4 CTAs -> exactly one wave

// Per-node precomputed readout vectors (one 128B line per node).
__device__ __align__(128) float g_prep[N_NODES * 32];
// L1 k8 frags: 8 frags x 32 lanes (uint = half2)
__device__ __align__(16) unsigned g_wfrags1[256];
// L2/L3/L4 k16 frags: 72 frags x 32 lanes (uint2)
__device__ __align__(16) uint2 g_wfrags2[2304];

// ---- SMEM layout (4-byte word offsets) ----
#define H2S     136          // hp row stride; 136 mod 32 == 8 -> conflict-free
#define CS_STR  132          // csm row stride; 132 mod 32 == 4 -> conflict-free tail
#define WF1_OFF 0            // 256 words
#define WF2_OFF 256          // 4608 words
#define HP_OFF  4864         // 32 pair-rows x 136 = 4352 words
#define CS_OFF  9216         // 16 rows x 132 = 2112 words
#define SMEM_WORDS 11328
#define SMEM_BYTES (SMEM_WORDS * 4)   // 45312 B -> 4 CTAs/SM

// frag bases inside wf2 (units of frags = 32 uint2)
#define FB_L2 0
#define FB_L3 32
#define FB_L4 64

__device__ __forceinline__ unsigned h2bits(__half2 h) { return *(unsigned*)&h; }

// silu via HW tanh, fully fp16x2: silu(x) = h + h*tanh(h), h = x/2.
__device__ __forceinline__ unsigned silu_h2(float x0, float x1) {
    __half2 h = __floats2half2_rn(x0, x1);
    __half2 hh = __hmul2(h, __floats2half2_rn(0.5f, 0.5f));
    unsigned t;
    asm("tanh.approx.f16x2 %0, %1;" : "=r"(t) : "r"(h2bits(hh)));
    __half2 r = __hfma2(hh, *(__half2*)&t, hh);
    return h2bits(r);
}

__device__ __forceinline__ void mma_f16(float* d, unsigned a0, unsigned a1,
                                        unsigned a2, unsigned a3,
                                        unsigned b0, unsigned b1) {
    asm volatile(
        "mma.sync.aligned.m16n8k16.row.col.f32.f16.f16.f32 "
        "{%0,%1,%2,%3}, {%4,%5,%6,%7}, {%8,%9}, {%0,%1,%2,%3};"
        : "+f"(d[0]), "+f"(d[1]), "+f"(d[2]), "+f"(d[3])
        : "r"(a0), "r"(a1), "r"(a2), "r"(a3), "r"(b0), "r"(b1));
}

__device__ __forceinline__ void mma_f16_k8(float* d, unsigned a0, unsigned a1, unsigned b0) {
    asm volatile(
        "mma.sync.aligned.m16n8k8.row.col.f32.f16.f16.f32 "
        "{%0,%1,%2,%3}, {%4,%5}, {%6}, {%0,%1,%2,%3};"
        : "+f"(d[0]), "+f"(d[1]), "+f"(d[2]), "+f"(d[3])
        : "r"(a0), "r"(a1), "r"(b0));
}

__device__ __forceinline__ void red1(float* a, float v) {
    asm volatile("red.global.add.f32 [%0], %1;" :: "l"(a), "f"(v) : "memory");
}

// ============================================================================
// Setup kernel: weight frag packing (low blocks) + per-node prep + out zero.
// ============================================================================
__global__ void __launch_bounds__(256)
setup_kernel(const float* __restrict__ nf,   // node_feats [N,256]
             const float* __restrict__ W0,   // [8,64]
             const float* __restrict__ W1,   // [8,64]
             const float* __restrict__ w1, const float* __restrict__ w2,
             const float* __restrict__ w3, const float* __restrict__ w4,
             float* __restrict__ out)
{
    const int tid = threadIdx.x;
    const float s8 = 0.3535533905932738f, s64 = 0.125f;

    int idx = blockIdx.x * 256 + tid;
    if (idx < 256) {
        int f = idx >> 5, lane = idx & 31;
        int c = lane & 3, g = lane >> 2;
        int n = f * 8 + g;
        __half2 p = __floats2half2_rn(w1[(2*c) * 64 + n] * s8,
                                      w1[(2*c + 1) * 64 + n] * s8);
        g_wfrags1[idx] = h2bits(p);
    } else if (idx < 2560) {
        int t = idx - 256;
        int f = t >> 5, lane = t & 31;
        int c = lane & 3, g = lane >> 2;
        const float* w; int ncols, NT, fl;
        if (f < 32)      { w = w2; ncols = 64; NT = 8; fl = f; }
        else if (f < 64) { w = w3; ncols = 64; NT = 8; fl = f - 32; }
        else             { w = w4; ncols = 16; NT = 2; fl = f - 64; }
        int kt = fl / NT, nt = fl - kt * NT;
        int n = nt * 8 + g, kb = kt * 16 + 2 * c;
        __half2 x = __floats2half2_rn(w[kb * ncols + n] * s64,
                                      w[(kb + 1) * ncols + n] * s64);
        __half2 y = __floats2half2_rn(w[(kb + 8) * ncols + n] * s64,
                                      w[(kb + 9) * ncols + n] * s64);
        g_wfrags2[t] = make_uint2(h2bits(x), h2bits(y));
    }

    // ---- per-node prep (warp per node) ----
    __shared__ float sW0[512], sW1[512];
    for (int i = tid; i < 512; i += 256) { sW0[i] = W0[i]; sW1[i] = W1[i]; }
    __syncthreads();

    const int warp = tid >> 5;
    const int lane = tid & 31;
    const int n = blockIdx.x * 8 + warp;
    if (n >= N_NODES) return;

    const float* nrow = nf + (size_t)n * 256;
    const int v1 = lane, v2 = lane + 32;
    float x1 = nrow[v1], x2 = nrow[v2];
    float y1[3], y2[3];
    #pragma unroll
    for (int k = 0; k < 3; k++) {
        y1[k] = nrow[64 + v1 * 3 + k];
        y2[k] = nrow[64 + v2 * 3 + k];
    }

    float P[32];
    #pragma unroll
    for (int u = 0; u < 8; u++)
        P[u] = fmaf(sW0[u * 64 + v1], x1, sW0[u * 64 + v2] * x2);
    #pragma unroll
    for (int u = 0; u < 8; u++) {
        float wa = sW1[u * 64 + v1], wb = sW1[u * 64 + v2];
        #pragma unroll
        for (int k = 0; k < 3; k++)
            P[8 + u * 3 + k] = fmaf(wa, y1[k], wb * y2[k]);
    }

    #pragma unroll
    for (int off = 16; off; off >>= 1) {
        #pragma unroll
        for (int j = 0; j < 32; j++)
            P[j] += __shfl_xor_sync(0xffffffffu, P[j], off);
    }

    if (lane == 0) {
        const float c0 = 0.03125f;                        // 1/sqrt(8*64*2)
        const float c1 = 0.03125f * 0.5773502691896258f;  // c/sqrt(3)
        float* dst = g_prep + (size_t)n * 32;
        #pragma unroll
        for (int j = 0; j < 8; j++)  dst[j] = P[j] * c0;
        #pragma unroll
        for (int j = 8; j < 32; j++) dst[j] = P[j] * c1;
        out[n] = 0.f;
    }
}

// k16 layer: warp computes 16 edges x NT*8 outputs over KT*16 K.
template<int KT, int NT>
__device__ __forceinline__ void mma_layer(const uint2* __restrict__ wf,
                                          const unsigned* __restrict__ hp,
                                          int m0, int lane, float acc[][4]) {
    const int c = lane & 3, g = lane >> 2;
    #pragma unroll
    for (int kt = 0; kt < KT; kt++) {
        unsigned a0 = hp[(kt * 8 + c)     * H2S + m0 + g];
        unsigned a1 = hp[(kt * 8 + c)     * H2S + m0 + g + 8];
        unsigned a2 = hp[(kt * 8 + c + 4) * H2S + m0 + g];
        unsigned a3 = hp[(kt * 8 + c + 4) * H2S + m0 + g + 8];
        #pragma unroll
        for (int nt = 0; nt < NT; nt++) {
            uint2 b = wf[(kt * NT + nt) * 32 + lane];
            mma_f16(acc[nt], a0, a1, a2, a3, b.x, b.y);
        }
    }
}

// No lead syncwarp: mma.sync is warp-collective, so all lanes' hp reads for
// this layer completed before any lane reaches these stores.
template<int NT>
__device__ __forceinline__ void store_acts_h(unsigned* hp, int m0, int lane,
                                             float acc[][4]) {
    const int c = lane & 3, g = lane >> 2;
    #pragma unroll
    for (int nt = 0; nt < NT; nt++) {
        hp[(nt * 4 + c) * H2S + m0 + g]     = silu_h2(acc[nt][0], acc[nt][1]);
        hp[(nt * 4 + c) * H2S + m0 + g + 8] = silu_h2(acc[nt][2], acc[nt][3]);
    }
    __syncwarp();   // stores visible before next layer's loads
}

__global__ void __launch_bounds__(256, 4)
edge_kernel(const float* __restrict__ ef,   // edge_feats [E,8]
            const float* __restrict__ ea,   // edge_attrs [E,4]
            const float* __restrict__ qi,   // charges_induced [N,8]
            const int*   __restrict__ eidx, // edge_index [2,E]
            float* __restrict__ out)
{
    extern __shared__ float smem[];
    unsigned* wf1 = (unsigned*)smem;
    uint2*    wf2 = (uint2*)(smem + WF2_OFF);
    unsigned* hp  = (unsigned*)(smem + HP_OFF);
    float*    csm = smem + CS_OFF;

    const int tid  = threadIdx.x;
    const int lane = tid & 31;
    const int m0   = (tid >> 5) * 16;
    const int half = lane & 1;
    const int cm   = m0 + (lane >> 1);   // this lane's edge column
    const int c    = lane & 3;
    const int g    = lane >> 2;

    // Weight frags -> SMEM (block-cooperative; the only block sync).
    {
        const float4* s1 = (const float4*)g_wfrags1;   // 64 float4
        float4* d1 = (float4*)smem;
        if (tid < 64) d1[tid] = s1[tid];
        const float4* s2 = (const float4*)g_wfrags2;   // 1152 float4
        float4* d2 = (float4*)(smem + WF2_OFF);
        #pragma unroll
        for (int i = 0; i < 4; i++) d2[tid + i * 256] = s2[tid + i * 256];
        if (tid < 128) d2[tid + 1024] = s2[tid + 1024];
    }
    __syncthreads();

    // Persistent grid-stride over 128-edge batches: bi, bi+GRID, ...
    int bi = blockIdx.x;

    // Prefetch first batch's indices.
    int s_n = eidx[bi * 128 + cm];
    int r_n = eidx[N_EDGES + bi * 128 + cm];

    float acc[8][4];
    #define ZACC(N) { _Pragma("unroll") for (int i = 0; i < N; i++) { \
        acc[i][0]=0.f; acc[i][1]=0.f; acc[i][2]=0.f; acc[i][3]=0.f; } }

    #pragma unroll 1
    for (; bi < NBATCH; bi += GRID) {
        const int s_ = s_n;
        const int r_ = r_n;
        const int me = bi * 128 + cm;

        // ---- Single parallel LDG round ----
        float4 at = *(const float4*)(ea + (size_t)me * 4);
        float4 f4 = *(const float4*)(ef + (size_t)me * 8 + half * 4);
        float4 q0 = *(const float4*)(qi + (size_t)s_ * 8);
        float4 q1 = *(const float4*)(qi + (size_t)s_ * 8 + 4);
        const float4* pr = (const float4*)(g_prep + (size_t)r_ * 32);

        // Prefetch next batch's indices.
        if (bi + GRID < NBATCH) {
            s_n = eidx[(bi + GRID) * 128 + cm];
            r_n = eidx[N_EDGES + (bi + GRID) * 128 + cm];
        }

        // Stage layer-1 inputs (hp pair-rows 0..3).
        hp[(2 * half)     * H2S + cm] = h2bits(__floats2half2_rn(f4.x, f4.y));
        hp[(2 * half + 1) * H2S + cm] = h2bits(__floats2half2_rn(f4.z, f4.w));

        // Contract gather into csm[16][edge] (stride 132).
        float q[8] = {q0.x, q0.y, q0.z, q0.w, q1.x, q1.y, q1.z, q1.w};
        if (half == 0) {
            float4 Aa = pr[0], Ab = pr[1];
            float A0[8] = {Aa.x, Aa.y, Aa.z, Aa.w, Ab.x, Ab.y, Ab.z, Ab.w};
            #pragma unroll
            for (int u = 0; u < 8; u++) csm[u * CS_STR + cm] = (q[u] * at.x) * A0[u];
        } else {
            float A1[24];
            #pragma unroll
            for (int i = 0; i < 6; i++) {
                float4 v = pr[2 + i];
                A1[4*i] = v.x; A1[4*i+1] = v.y; A1[4*i+2] = v.z; A1[4*i+3] = v.w;
            }
            #pragma unroll
            for (int u = 0; u < 8; u++) {
                float bs = at.y * A1[3*u];
                bs = fmaf(at.z, A1[3*u + 1], bs);
                bs = fmaf(at.w, A1[3*u + 2], bs);
                csm[(8 + u) * CS_STR + cm] = q[u] * bs;
            }
        }
        __syncwarp();

        // ---- Layer 1: 8 -> 64 (k8) ----
        ZACC(8);
        {
            unsigned a0 = hp[c * H2S + m0 + g];
            unsigned a1 = hp[c * H2S + m0 + g + 8];
            #pragma unroll
            for (int nt = 0; nt < 8; nt++)
                mma_f16_k8(acc[nt], a0, a1, wf1[nt * 32 + lane]);
        }
        store_acts_h<8>(hp, m0, lane, acc);

        ZACC(8); mma_layer<4, 8>(wf2 + FB_L2 * 32, hp, m0, lane, acc);
        store_acts_h<8>(hp, m0, lane, acc);

        ZACC(8); mma_layer<4, 8>(wf2 + FB_L3 * 32, hp, m0, lane, acc);
        store_acts_h<8>(hp, m0, lane, acc);

        // ---- Layer 4: 64 -> 16, tail directly in D-fragment domain ----
        ZACC(2); mma_layer<4, 2>(wf2 + FB_L4 * 32, hp, m0, lane, acc);

        // Thread (g,c) holds tp rows {g, g+8} x cols {nt*8+2c, nt*8+2c+1}.
        const float* cg  = csm + m0 + g;
        const float* cg8 = csm + m0 + g + 8;
        float sA = acc[0][0] * cg[(2*c)     * CS_STR]
                 + acc[0][1] * cg[(2*c + 1) * CS_STR]
                 + acc[1][0] * cg[(8 + 2*c) * CS_STR]
                 + acc[1][1] * cg[(9 + 2*c) * CS_STR];
        float sB = acc[0][2] * cg8[(2*c)     * CS_STR]
                 + acc[0][3] * cg8[(2*c + 1) * CS_STR]
                 + acc[1][2] * cg8[(8 + 2*c) * CS_STR]
                 + acc[1][3] * cg8[(9 + 2*c) * CS_STR];
        sA += __shfl_xor_sync(0xffffffffu, sA, 1);
        sA += __shfl_xor_sync(0xffffffffu, sA, 2);
        sB += __shfl_xor_sync(0xffffffffu, sB, 1);
        sB += __shfl_xor_sync(0xffffffffu, sB, 2);
        int rg  = __shfl_sync(0xffffffffu, r_, 2 * g);
        int rg8 = __shfl_sync(0xffffffffu, r_, 2 * g + 16);
        if (c == 0) {
            red1(out + rg,  sA);
            red1(out + rg8, sB);
        }
        __syncwarp();   // tail csm reads done before next batch overwrites
    }
}

extern "C" void kernel_launch(void* const* d_in, const int* in_sizes, int n_in,
                              void* d_out, int out_size)
{
    const float* node_feats      = (const float*)d_in[0];
    const float* charges_induced = (const float*)d_in[2];
    const float* edge_feats      = (const float*)d_in[3];
    const float* edge_attrs      = (const float*)d_in[4];
    const float* mlp_w1          = (const float*)d_in[6];
    const float* mlp_w2          = (const float*)d_in[7];
    const float* mlp_w3          = (const float*)d_in[8];
    const float* mlp_w4          = (const float*)d_in[9];
    const float* W0              = (const float*)d_in[10];
    const float* W1              = (const float*)d_in[11];
    const int*   eidx            = (const int*)d_in[12];
    float* out = (float*)d_out;

    setup_kernel<<<(N_NODES + 7) / 8, 256>>>(node_feats, W0, W1,
                                             mlp_w1, mlp_w2, mlp_w3, mlp_w4, out);

    cudaFuncSetAttribute(edge_kernel, cudaFuncAttributeMaxDynamicSharedMemorySize, SMEM_BYTES);
    edge_kernel<<<GRID, 256, SMEM_BYTES>>>(
        edge_feats, edge_attrs, charges_induced, eidx, out);
}

// round 15
// speedup vs baseline: 1.5582x; 1.1608x over previous
#include <cuda_runtime.h>
#include <cuda_fp16.h>

#define N_NODES 50000
#define N_EDGES 1600000
#define NBATCH  12500        // total 128-edge batches
#define GRID    592          // 148 SMs x 4 CTAs -> exactly one wave

// Per-node precomputed readout vectors (one 128B line per node).
__device__ __align__(128) float g_prep[N_NODES * 32];
// L1 k8 frags: 8 frags x 32 lanes (uint = half2)
__device__ __align__(16) unsigned g_wfrags1[256];
// L2/L3/L4 k16 frags: 72 frags x 32 lanes (uint2)
__device__ __align__(16) uint2 g_wfrags2[2304];

// ---- SMEM layout (4-byte word offsets) ----
#define CS_STR  132          // csm row stride; 132 mod 32 == 4 -> conflict-free tail
#define WF1_OFF 0            // 256 words
#define WF2_OFF 256          // 4608 words
#define CS_OFF  4864         // 16 rows x 132 = 2112 words
#define SMEM_WORDS (CS_OFF + 16 * CS_STR)
#define SMEM_BYTES (SMEM_WORDS * 4)   // 27904 B; residency capped by RF at 4 CTAs

// frag bases inside wf2 (units of frags = 32 uint2)
#define FB_L2 0
#define FB_L3 32
#define FB_L4 64

__device__ __forceinline__ unsigned h2bits(__half2 h) { return *(unsigned*)&h; }

// silu via HW tanh, fully fp16x2: silu(x) = h + h*tanh(h), h = x/2.
__device__ __forceinline__ unsigned silu_h2(float x0, float x1) {
    __half2 h = __floats2half2_rn(x0, x1);
    __half2 hh = __hmul2(h, __floats2half2_rn(0.5f, 0.5f));
    unsigned t;
    asm("tanh.approx.f16x2 %0, %1;" : "=r"(t) : "r"(h2bits(hh)));
    __half2 r = __hfma2(hh, *(__half2*)&t, hh);
    return h2bits(r);
}

__device__ __forceinline__ void mma_f16(float* d, unsigned a0, unsigned a1,
                                        unsigned a2, unsigned a3,
                                        unsigned b0, unsigned b1) {
    asm volatile(
        "mma.sync.aligned.m16n8k16.row.col.f32.f16.f16.f32 "
        "{%0,%1,%2,%3}, {%4,%5,%6,%7}, {%8,%9}, {%0,%1,%2,%3};"
        : "+f"(d[0]), "+f"(d[1]), "+f"(d[2]), "+f"(d[3])
        : "r"(a0), "r"(a1), "r"(a2), "r"(a3), "r"(b0), "r"(b1));
}

__device__ __forceinline__ void mma_f16_k8(float* d, unsigned a0, unsigned a1, unsigned b0) {
    asm volatile(
        "mma.sync.aligned.m16n8k8.row.col.f32.f16.f16.f32 "
        "{%0,%1,%2,%3}, {%4,%5}, {%6}, {%0,%1,%2,%3};"
        : "+f"(d[0]), "+f"(d[1]), "+f"(d[2]), "+f"(d[3])
        : "r"(a0), "r"(a1), "r"(b0));
}

__device__ __forceinline__ void red1(float* a, float v) {
    asm volatile("red.global.add.f32 [%0], %1;" :: "l"(a), "f"(v) : "memory");
}

// ============================================================================
// Setup kernel: weight frag packing (low blocks) + per-node prep + out zero.
// ============================================================================
__global__ void __launch_bounds__(256)
setup_kernel(const float* __restrict__ nf,   // node_feats [N,256]
             const float* __restrict__ W0,   // [8,64]
             const float* __restrict__ W1,   // [8,64]
             const float* __restrict__ w1, const float* __restrict__ w2,
             const float* __restrict__ w3, const float* __restrict__ w4,
             float* __restrict__ out)
{
    const int tid = threadIdx.x;
    const float s8 = 0.3535533905932738f, s64 = 0.125f;

    int idx = blockIdx.x * 256 + tid;
    if (idx < 256) {
        int f = idx >> 5, lane = idx & 31;
        int c = lane & 3, g = lane >> 2;
        int n = f * 8 + g;
        __half2 p = __floats2half2_rn(w1[(2*c) * 64 + n] * s8,
                                      w1[(2*c + 1) * 64 + n] * s8);
        g_wfrags1[idx] = h2bits(p);
    } else if (idx < 2560) {
        int t = idx - 256;
        int f = t >> 5, lane = t & 31;
        int c = lane & 3, g = lane >> 2;
        const float* w; int ncols, NT, fl;
        if (f < 32)      { w = w2; ncols = 64; NT = 8; fl = f; }
        else if (f < 64) { w = w3; ncols = 64; NT = 8; fl = f - 32; }
        else             { w = w4; ncols = 16; NT = 2; fl = f - 64; }
        int kt = fl / NT, nt = fl - kt * NT;
        int n = nt * 8 + g, kb = kt * 16 + 2 * c;
        __half2 x = __floats2half2_rn(w[kb * ncols + n] * s64,
                                      w[(kb + 1) * ncols + n] * s64);
        __half2 y = __floats2half2_rn(w[(kb + 8) * ncols + n] * s64,
                                      w[(kb + 9) * ncols + n] * s64);
        g_wfrags2[t] = make_uint2(h2bits(x), h2bits(y));
    }

    // ---- per-node prep (warp per node) ----
    __shared__ float sW0[512], sW1[512];
    for (int i = tid; i < 512; i += 256) { sW0[i] = W0[i]; sW1[i] = W1[i]; }
    __syncthreads();

    const int warp = tid >> 5;
    const int lane = tid & 31;
    const int n = blockIdx.x * 8 + warp;
    if (n >= N_NODES) return;

    const float* nrow = nf + (size_t)n * 256;
    const int v1 = lane, v2 = lane + 32;
    float x1 = nrow[v1], x2 = nrow[v2];
    float y1[3], y2[3];
    #pragma unroll
    for (int k = 0; k < 3; k++) {
        y1[k] = nrow[64 + v1 * 3 + k];
        y2[k] = nrow[64 + v2 * 3 + k];
    }

    float P[32];
    #pragma unroll
    for (int u = 0; u < 8; u++)
        P[u] = fmaf(sW0[u * 64 + v1], x1, sW0[u * 64 + v2] * x2);
    #pragma unroll
    for (int u = 0; u < 8; u++) {
        float wa = sW1[u * 64 + v1], wb = sW1[u * 64 + v2];
        #pragma unroll
        for (int k = 0; k < 3; k++)
            P[8 + u * 3 + k] = fmaf(wa, y1[k], wb * y2[k]);
    }

    #pragma unroll
    for (int off = 16; off; off >>= 1) {
        #pragma unroll
        for (int j = 0; j < 32; j++)
            P[j] += __shfl_xor_sync(0xffffffffu, P[j], off);
    }

    if (lane == 0) {
        const float c0 = 0.03125f;                        // 1/sqrt(8*64*2)
        const float c1 = 0.03125f * 0.5773502691896258f;  // c/sqrt(3)
        float* dst = g_prep + (size_t)n * 32;
        #pragma unroll
        for (int j = 0; j < 8; j++)  dst[j] = P[j] * c0;
        #pragma unroll
        for (int j = 8; j < 32; j++) dst[j] = P[j] * c1;
        out[n] = 0.f;
    }
}

// ============================================================================
// Edge kernel: register-resident activation chain on the 64-reg/4-CTA frontier.
// D-frag of layer l IS the A-frag of layer l+1 (same thread, same order).
// ============================================================================
__global__ void __launch_bounds__(256, 4)
edge_kernel(const float* __restrict__ ef,   // edge_feats [E,8]
            const float* __restrict__ ea,   // edge_attrs [E,4]
            const float* __restrict__ qi,   // charges_induced [N,8]
            const int*   __restrict__ eidx, // edge_index [2,E]
            float* __restrict__ out)
{
    extern __shared__ float smem[];
    unsigned* wf1 = (unsigned*)smem;
    uint2*    wf2 = (uint2*)(smem + WF2_OFF);
    float*    csm = smem + CS_OFF;

    const int tid  = threadIdx.x;
    const int lane = tid & 31;
    const int m0   = (tid >> 5) * 16;
    const int half = lane & 1;
    const int cm   = m0 + (lane >> 1);   // this lane's edge column
    const int c    = lane & 3;
    const int g    = lane >> 2;

    // Weight frags -> SMEM (block-cooperative; the only block sync).
    {
        const float4* s1 = (const float4*)g_wfrags1;   // 64 float4
        float4* d1 = (float4*)smem;
        if (tid < 64) d1[tid] = s1[tid];
        const float4* s2 = (const float4*)g_wfrags2;   // 1152 float4
        float4* d2 = (float4*)(smem + WF2_OFF);
        #pragma unroll
        for (int i = 0; i < 4; i++) d2[tid + i * 256] = s2[tid + i * 256];
        if (tid < 128) d2[tid + 1024] = s2[tid + 1024];
    }
    __syncthreads();

    float acc[8][4];
    #define ZACC(N) { _Pragma("unroll") for (int i = 0; i < N; i++) { \
        acc[i][0]=0.f; acc[i][1]=0.f; acc[i][2]=0.f; acc[i][3]=0.f; } }

    // Persistent grid-stride over 128-edge batches.
    #pragma unroll 1
    for (int bi = blockIdx.x; bi < NBATCH; bi += GRID) {
        const int me = bi * 128 + cm;
        const int e0 = bi * 128 + m0;

        // ---- Gather ----
        const int s_ = eidx[me];
        const int r_ = eidx[N_EDGES + me];
        float4 at = *(const float4*)(ea + (size_t)me * 4);
        float2 fa = *(const float2*)(ef + (size_t)(e0 + g) * 8 + 2 * c);
        float2 fb = *(const float2*)(ef + (size_t)(e0 + g + 8) * 8 + 2 * c);
        float4 q0 = *(const float4*)(qi + (size_t)s_ * 8);
        float4 q1 = *(const float4*)(qi + (size_t)s_ * 8 + 4);
        const float4* pr = (const float4*)(g_prep + (size_t)r_ * 32);

        // Contract gather into csm[16][edge] (stride 132).
        float q[8] = {q0.x, q0.y, q0.z, q0.w, q1.x, q1.y, q1.z, q1.w};
        if (half == 0) {
            float4 Aa = pr[0], Ab = pr[1];
            float A0[8] = {Aa.x, Aa.y, Aa.z, Aa.w, Ab.x, Ab.y, Ab.z, Ab.w};
            #pragma unroll
            for (int u = 0; u < 8; u++) csm[u * CS_STR + cm] = (q[u] * at.x) * A0[u];
        } else {
            float A1[24];
            #pragma unroll
            for (int i = 0; i < 6; i++) {
                float4 v = pr[2 + i];
                A1[4*i] = v.x; A1[4*i+1] = v.y; A1[4*i+2] = v.z; A1[4*i+3] = v.w;
            }
            #pragma unroll
            for (int u = 0; u < 8; u++) {
                float bs = at.y * A1[3*u];
                bs = fmaf(at.z, A1[3*u + 1], bs);
                bs = fmaf(at.w, A1[3*u + 2], bs);
                csm[(8 + u) * CS_STR + cm] = q[u] * bs;
            }
        }
        __syncwarp();

        // ---- Layer 1: 8 -> 64 (k8; A direct from gmem) ----
        unsigned a0 = h2bits(__floats2half2_rn(fa.x, fa.y));
        unsigned a1 = h2bits(__floats2half2_rn(fb.x, fb.y));
        ZACC(8);
        #pragma unroll
        for (int nt = 0; nt < 8; nt++)
            mma_f16_k8(acc[nt], a0, a1, wf1[nt * 32 + lane]);

        unsigned hlo[8], hhi[8];
        #pragma unroll
        for (int nt = 0; nt < 8; nt++) {
            hlo[nt] = silu_h2(acc[nt][0], acc[nt][1]);
            hhi[nt] = silu_h2(acc[nt][2], acc[nt][3]);
        }

        // ---- Layer 2: 64 -> 64 (register chain) ----
        ZACC(8);
        #pragma unroll
        for (int kt = 0; kt < 4; kt++) {
            unsigned A0 = hlo[2*kt], A1 = hhi[2*kt];
            unsigned A2 = hlo[2*kt+1], A3 = hhi[2*kt+1];
            #pragma unroll
            for (int nt = 0; nt < 8; nt++) {
                uint2 b = wf2[(FB_L2 + kt * 8 + nt) * 32 + lane];
                mma_f16(acc[nt], A0, A1, A2, A3, b.x, b.y);
            }
        }
        #pragma unroll
        for (int nt = 0; nt < 8; nt++) {
            hlo[nt] = silu_h2(acc[nt][0], acc[nt][1]);
            hhi[nt] = silu_h2(acc[nt][2], acc[nt][3]);
        }

        // ---- Layer 3: 64 -> 64 ----
        ZACC(8);
        #pragma unroll
        for (int kt = 0; kt < 4; kt++) {
            unsigned A0 = hlo[2*kt], A1 = hhi[2*kt];
            unsigned A2 = hlo[2*kt+1], A3 = hhi[2*kt+1];
            #pragma unroll
            for (int nt = 0; nt < 8; nt++) {
                uint2 b = wf2[(FB_L3 + kt * 8 + nt) * 32 + lane];
                mma_f16(acc[nt], A0, A1, A2, A3, b.x, b.y);
            }
        }
        #pragma unroll
        for (int nt = 0; nt < 8; nt++) {
            hlo[nt] = silu_h2(acc[nt][0], acc[nt][1]);
            hhi[nt] = silu_h2(acc[nt][2], acc[nt][3]);
        }

        // ---- Layer 4: 64 -> 16 (no activation) ----
        ZACC(2);
        #pragma unroll
        for (int kt = 0; kt < 4; kt++) {
            unsigned A0 = hlo[2*kt], A1 = hhi[2*kt];
            unsigned A2 = hlo[2*kt+1], A3 = hhi[2*kt+1];
            #pragma unroll
            for (int nt = 0; nt < 2; nt++) {
                uint2 b = wf2[(FB_L4 + kt * 2 + nt) * 32 + lane];
                mma_f16(acc[nt], A0, A1, A2, A3, b.x, b.y);
            }
        }

        // ---- Tail: dot(tp, C) in D-fragment domain ----
        // Thread (g,c) holds tp rows {g, g+8} x cols {nt*8+2c, nt*8+2c+1}.
        const float* cg  = csm + m0 + g;
        const float* cg8 = csm + m0 + g + 8;
        float sA = acc[0][0] * cg[(2*c)     * CS_STR]
                 + acc[0][1] * cg[(2*c + 1) * CS_STR]
                 + acc[1][0] * cg[(8 + 2*c) * CS_STR]
                 + acc[1][1] * cg[(9 + 2*c) * CS_STR];
        float sB = acc[0][2] * cg8[(2*c)     * CS_STR]
                 + acc[0][3] * cg8[(2*c + 1) * CS_STR]
                 + acc[1][2] * cg8[(8 + 2*c) * CS_STR]
                 + acc[1][3] * cg8[(9 + 2*c) * CS_STR];
        sA += __shfl_xor_sync(0xffffffffu, sA, 1);
        sA += __shfl_xor_sync(0xffffffffu, sA, 2);
        sB += __shfl_xor_sync(0xffffffffu, sB, 1);
        sB += __shfl_xor_sync(0xffffffffu, sB, 2);
        int rg  = __shfl_sync(0xffffffffu, r_, 2 * g);
        int rg8 = __shfl_sync(0xffffffffu, r_, 2 * g + 16);
        if (c == 0) {
            red1(out + rg,  sA);
            red1(out + rg8, sB);
        }
        __syncwarp();   // tail csm reads done before next batch overwrites
    }
}

extern "C" void kernel_launch(void* const* d_in, const int* in_sizes, int n_in,
                              void* d_out, int out_size)
{
    const float* node_feats      = (const float*)d_in[0];
    const float* charges_induced = (const float*)d_in[2];
    const float* edge_feats      = (const float*)d_in[3];
    const float* edge_attrs      = (const float*)d_in[4];
    const float* mlp_w1          = (const float*)d_in[6];
    const float* mlp_w2          = (const float*)d_in[7];
    const float* mlp_w3          = (const float*)d_in[8];
    const float* mlp_w4          = (const float*)d_in[9];
    const float* W0              = (const float*)d_in[10];
    const float* W1              = (const float*)d_in[11];
    const int*   eidx            = (const int*)d_in[12];
    float* out = (float*)d_out;

    setup_kernel<<<(N_NODES + 7) / 8, 256>>>(node_feats, W0, W1,
                                             mlp_w1, mlp_w2, mlp_w3, mlp_w4, out);

    cudaFuncSetAttribute(edge_kernel, cudaFuncAttributeMaxDynamicSharedMemorySize, SMEM_BYTES);
    edge_kernel<<<GRID, 256, SMEM_BYTES>>>(
        edge_feats, edge_attrs, charges_induced, eidx, out);
}

// round 16
// speedup vs baseline: 1.6371x; 1.0506x over previous
#include <cuda_runtime.h>
#include <cuda_fp16.h>

#define N_NODES 50000
#define N_EDGES 1600000
#define NBATCH  12500        // total 128-edge batches
#define GRID    592          // 148 SMs x 4 CTAs -> exactly one wave

// Per-node precomputed readout vectors (one 128B line per node).
__device__ __align__(128) float g_prep[N_NODES * 32];
// L1 k8 frags: 8 frags x 32 lanes (uint = half2)
__device__ __align__(16) unsigned g_wfrags1[256];
// L2/L3/L4 k16 frags: 72 frags x 32 lanes (uint2)
__device__ __align__(16) uint2 g_wfrags2[2304];

// ---- SMEM layout (4-byte word offsets) ----
#define CS_STR  132          // csm row stride; 132 mod 32 == 4 -> conflict-free tail
#define WF1_OFF 0            // 256 words
#define WF2_OFF 256          // 4608 words
#define CS_OFF  4864         // 16 rows x 132 = 2112 words
#define PR_OFF  6976         // per-warp praw: 16 edges x 36 floats (16B-aligned rows)
#define PR_WSTR 576          // words per warp block
#define SMEM_WORDS (PR_OFF + 8 * PR_WSTR)
#define SMEM_BYTES (SMEM_WORDS * 4)   // 46336 B; 4 CTAs fit (185KB < 228KB)

// frag bases inside wf2 (units of frags = 32 uint2)
#define FB_L2 0
#define FB_L3 32
#define FB_L4 64

__device__ __forceinline__ unsigned h2bits(__half2 h) { return *(unsigned*)&h; }

// silu via HW tanh, fully fp16x2: silu(x) = h + h*tanh(h), h = x/2.
__device__ __forceinline__ unsigned silu_h2(float x0, float x1) {
    __half2 h = __floats2half2_rn(x0, x1);
    __half2 hh = __hmul2(h, __floats2half2_rn(0.5f, 0.5f));
    unsigned t;
    asm("tanh.approx.f16x2 %0, %1;" : "=r"(t) : "r"(h2bits(hh)));
    __half2 r = __hfma2(hh, *(__half2*)&t, hh);
    return h2bits(r);
}

__device__ __forceinline__ void mma_f16(float* d, unsigned a0, unsigned a1,
                                        unsigned a2, unsigned a3,
                                        unsigned b0, unsigned b1) {
    asm volatile(
        "mma.sync.aligned.m16n8k16.row.col.f32.f16.f16.f32 "
        "{%0,%1,%2,%3}, {%4,%5,%6,%7}, {%8,%9}, {%0,%1,%2,%3};"
        : "+f"(d[0]), "+f"(d[1]), "+f"(d[2]), "+f"(d[3])
        : "r"(a0), "r"(a1), "r"(a2), "r"(a3), "r"(b0), "r"(b1));
}

__device__ __forceinline__ void mma_f16_k8(float* d, unsigned a0, unsigned a1, unsigned b0) {
    asm volatile(
        "mma.sync.aligned.m16n8k8.row.col.f32.f16.f16.f32 "
        "{%0,%1,%2,%3}, {%4,%5}, {%6}, {%0,%1,%2,%3};"
        : "+f"(d[0]), "+f"(d[1]), "+f"(d[2]), "+f"(d[3])
        : "r"(a0), "r"(a1), "r"(b0));
}

__device__ __forceinline__ void red1(float* a, float v) {
    asm volatile("red.global.add.f32 [%0], %1;" :: "l"(a), "f"(v) : "memory");
}

// ============================================================================
// Setup kernel: weight frag packing (low blocks) + per-node prep + out zero.
// ============================================================================
__global__ void __launch_bounds__(256)
setup_kernel(const float* __restrict__ nf,   // node_feats [N,256]
             const float* __restrict__ W0,   // [8,64]
             const float* __restrict__ W1,   // [8,64]
             const float* __restrict__ w1, const float* __restrict__ w2,
             const float* __restrict__ w3, const float* __restrict__ w4,
             float* __restrict__ out)
{
    const int tid = threadIdx.x;
    const float s8 = 0.3535533905932738f, s64 = 0.125f;

    int idx = blockIdx.x * 256 + tid;
    if (idx < 256) {
        int f = idx >> 5, lane = idx & 31;
        int c = lane & 3, g = lane >> 2;
        int n = f * 8 + g;
        __half2 p = __floats2half2_rn(w1[(2*c) * 64 + n] * s8,
                                      w1[(2*c + 1) * 64 + n] * s8);
        g_wfrags1[idx] = h2bits(p);
    } else if (idx < 2560) {
        int t = idx - 256;
        int f = t >> 5, lane = t & 31;
        int c = lane & 3, g = lane >> 2;
        const float* w; int ncols, NT, fl;
        if (f < 32)      { w = w2; ncols = 64; NT = 8; fl = f; }
        else if (f < 64) { w = w3; ncols = 64; NT = 8; fl = f - 32; }
        else             { w = w4; ncols = 16; NT = 2; fl = f - 64; }
        int kt = fl / NT, nt = fl - kt * NT;
        int n = nt * 8 + g, kb = kt * 16 + 2 * c;
        __half2 x = __floats2half2_rn(w[kb * ncols + n] * s64,
                                      w[(kb + 1) * ncols + n] * s64);
        __half2 y = __floats2half2_rn(w[(kb + 8) * ncols + n] * s64,
                                      w[(kb + 9) * ncols + n] * s64);
        g_wfrags2[t] = make_uint2(h2bits(x), h2bits(y));
    }

    // ---- per-node prep (warp per node) ----
    __shared__ float sW0[512], sW1[512];
    for (int i = tid; i < 512; i += 256) { sW0[i] = W0[i]; sW1[i] = W1[i]; }
    __syncthreads();

    const int warp = tid >> 5;
    const int lane = tid & 31;
    const int n = blockIdx.x * 8 + warp;
    if (n >= N_NODES) return;

    const float* nrow = nf + (size_t)n * 256;
    const int v1 = lane, v2 = lane + 32;
    float x1 = nrow[v1], x2 = nrow[v2];
    float y1[3], y2[3];
    #pragma unroll
    for (int k = 0; k < 3; k++) {
        y1[k] = nrow[64 + v1 * 3 + k];
        y2[k] = nrow[64 + v2 * 3 + k];
    }

    float P[32];
    #pragma unroll
    for (int u = 0; u < 8; u++)
        P[u] = fmaf(sW0[u * 64 + v1], x1, sW0[u * 64 + v2] * x2);
    #pragma unroll
    for (int u = 0; u < 8; u++) {
        float wa = sW1[u * 64 + v1], wb = sW1[u * 64 + v2];
        #pragma unroll
        for (int k = 0; k < 3; k++)
            P[8 + u * 3 + k] = fmaf(wa, y1[k], wb * y2[k]);
    }

    #pragma unroll
    for (int off = 16; off; off >>= 1) {
        #pragma unroll
        for (int j = 0; j < 32; j++)
            P[j] += __shfl_xor_sync(0xffffffffu, P[j], off);
    }

    if (lane == 0) {
        const float c0 = 0.03125f;                        // 1/sqrt(8*64*2)
        const float c1 = 0.03125f * 0.5773502691896258f;  // c/sqrt(3)
        float* dst = g_prep + (size_t)n * 32;
        #pragma unroll
        for (int j = 0; j < 8; j++)  dst[j] = P[j] * c0;
        #pragma unroll
        for (int j = 8; j < 32; j++) dst[j] = P[j] * c1;
        out[n] = 0.f;
    }
}

// ============================================================================
// Edge kernel: register-resident MLP chain + coalesced prep gather via SMEM.
// ============================================================================
__global__ void __launch_bounds__(256, 4)
edge_kernel(const float* __restrict__ ef,   // edge_feats [E,8]
            const float* __restrict__ ea,   // edge_attrs [E,4]
            const float* __restrict__ qi,   // charges_induced [N,8]
            const int*   __restrict__ eidx, // edge_index [2,E]
            float* __restrict__ out)
{
    extern __shared__ float smem[];
    unsigned* wf1  = (unsigned*)smem;
    uint2*    wf2  = (uint2*)(smem + WF2_OFF);
    float*    csm  = smem + CS_OFF;
    float*    praw = smem + PR_OFF + (threadIdx.x >> 5) * PR_WSTR;

    const int tid  = threadIdx.x;
    const int lane = tid & 31;
    const int m0   = (tid >> 5) * 16;
    const int half = lane & 1;
    const int cm   = m0 + (lane >> 1);   // this lane's edge column
    const int c    = lane & 3;
    const int g    = lane >> 2;
    const unsigned FULL = 0xffffffffu;

    // Weight frags -> SMEM (block-cooperative; the only block sync).
    {
        const float4* s1 = (const float4*)g_wfrags1;   // 64 float4
        float4* d1 = (float4*)smem;
        if (tid < 64) d1[tid] = s1[tid];
        const float4* s2 = (const float4*)g_wfrags2;   // 1152 float4
        float4* d2 = (float4*)(smem + WF2_OFF);
        #pragma unroll
        for (int i = 0; i < 4; i++) d2[tid + i * 256] = s2[tid + i * 256];
        if (tid < 128) d2[tid + 1024] = s2[tid + 1024];
    }
    __syncthreads();

    float acc[8][4];
    #define ZACC(N) { _Pragma("unroll") for (int i = 0; i < N; i++) { \
        acc[i][0]=0.f; acc[i][1]=0.f; acc[i][2]=0.f; acc[i][3]=0.f; } }

    // Persistent grid-stride over 128-edge batches.
    #pragma unroll 1
    for (int bi = blockIdx.x; bi < NBATCH; bi += GRID) {
        const int me = bi * 128 + cm;
        const int e0 = bi * 128 + m0;

        // ---- Gather ----
        const int s_ = eidx[me];
        const int r_ = eidx[N_EDGES + me];
        float4 at = *(const float4*)(ea + (size_t)me * 4);
        float2 fa = *(const float2*)(ef + (size_t)(e0 + g) * 8 + 2 * c);
        float2 fb = *(const float2*)(ef + (size_t)(e0 + g + 8) * 8 + 2 * c);
        float4 q0 = *(const float4*)(qi + (size_t)s_ * 8);
        float4 q1 = *(const float4*)(qi + (size_t)s_ * 8 + 4);

        // Coalesced prep fetch: 8 lanes per edge, 4 rounds. Each LDG.128
        // instruction covers 4 whole 128B node rows (fully coalesced).
        #pragma unroll
        for (int t = 0; t < 4; t++) {
            int E  = t * 4 + (lane >> 3);               // edge 0..15
            int rE = __shfl_sync(FULL, r_, 2 * E);      // receiver of edge E
            float4 v = *(const float4*)(g_prep + (size_t)rE * 32 + (lane & 7) * 4);
            *(float4*)(praw + E * 36 + (lane & 7) * 4) = v;
        }
        __syncwarp();

        // Contract gather into csm[16][edge] (A values now from SMEM praw).
        const float* pw = praw + (lane >> 1) * 36;
        float q[8] = {q0.x, q0.y, q0.z, q0.w, q1.x, q1.y, q1.z, q1.w};
        if (half == 0) {
            float4 Aa = *(const float4*)pw;
            float4 Ab = *(const float4*)(pw + 4);
            float A0[8] = {Aa.x, Aa.y, Aa.z, Aa.w, Ab.x, Ab.y, Ab.z, Ab.w};
            #pragma unroll
            for (int u = 0; u < 8; u++) csm[u * CS_STR + cm] = (q[u] * at.x) * A0[u];
        } else {
            float A1[24];
            #pragma unroll
            for (int i = 0; i < 6; i++) {
                float4 v = *(const float4*)(pw + 8 + 4 * i);
                A1[4*i] = v.x; A1[4*i+1] = v.y; A1[4*i+2] = v.z; A1[4*i+3] = v.w;
            }
            #pragma unroll
            for (int u = 0; u < 8; u++) {
                float bs = at.y * A1[3*u];
                bs = fmaf(at.z, A1[3*u + 1], bs);
                bs = fmaf(at.w, A1[3*u + 2], bs);
                csm[(8 + u) * CS_STR + cm] = q[u] * bs;
            }
        }
        __syncwarp();

        // ---- Layer 1: 8 -> 64 (k8; A direct from gmem) ----
        unsigned a0 = h2bits(__floats2half2_rn(fa.x, fa.y));
        unsigned a1 = h2bits(__floats2half2_rn(fb.x, fb.y));
        ZACC(8);
        #pragma unroll
        for (int nt = 0; nt < 8; nt++)
            mma_f16_k8(acc[nt], a0, a1, wf1[nt * 32 + lane]);

        unsigned hlo[8], hhi[8];
        #pragma unroll
        for (int nt = 0; nt < 8; nt++) {
            hlo[nt] = silu_h2(acc[nt][0], acc[nt][1]);
            hhi[nt] = silu_h2(acc[nt][2], acc[nt][3]);
        }

        // ---- Layer 2: 64 -> 64 (register chain) ----
        ZACC(8);
        #pragma unroll
        for (int kt = 0; kt < 4; kt++) {
            unsigned A0 = hlo[2*kt], A1 = hhi[2*kt];
            unsigned A2 = hlo[2*kt+1], A3 = hhi[2*kt+1];
            #pragma unroll
            for (int nt = 0; nt < 8; nt++) {
                uint2 b = wf2[(FB_L2 + kt * 8 + nt) * 32 + lane];
                mma_f16(acc[nt], A0, A1, A2, A3, b.x, b.y);
            }
        }
        #pragma unroll
        for (int nt = 0; nt < 8; nt++) {
            hlo[nt] = silu_h2(acc[nt][0], acc[nt][1]);
            hhi[nt] = silu_h2(acc[nt][2], acc[nt][3]);
        }

        // ---- Layer 3: 64 -> 64 ----
        ZACC(8);
        #pragma unroll
        for (int kt = 0; kt < 4; kt++) {
            unsigned A0 = hlo[2*kt], A1 = hhi[2*kt];
            unsigned A2 = hlo[2*kt+1], A3 = hhi[2*kt+1];
            #pragma unroll
            for (int nt = 0; nt < 8; nt++) {
                uint2 b = wf2[(FB_L3 + kt * 8 + nt) * 32 + lane];
                mma_f16(acc[nt], A0, A1, A2, A3, b.x, b.y);
            }
        }
        #pragma unroll
        for (int nt = 0; nt < 8; nt++) {
            hlo[nt] = silu_h2(acc[nt][0], acc[nt][1]);
            hhi[nt] = silu_h2(acc[nt][2], acc[nt][3]);
        }

        // ---- Layer 4: 64 -> 16 (no activation) ----
        ZACC(2);
        #pragma unroll
        for (int kt = 0; kt < 4; kt++) {
            unsigned A0 = hlo[2*kt], A1 = hhi[2*kt];
            unsigned A2 = hlo[2*kt+1], A3 = hhi[2*kt+1];
            #pragma unroll
            for (int nt = 0; nt < 2; nt++) {
                uint2 b = wf2[(FB_L4 + kt * 2 + nt) * 32 + lane];
                mma_f16(acc[nt], A0, A1, A2, A3, b.x, b.y);
            }
        }

        // ---- Tail: dot(tp, C) in D-fragment domain ----
        const float* cg  = csm + m0 + g;
        const float* cg8 = csm + m0 + g + 8;
        float sA = acc[0][0] * cg[(2*c)     * CS_STR]
                 + acc[0][1] * cg[(2*c + 1) * CS_STR]
                 + acc[1][0] * cg[(8 + 2*c) * CS_STR]
                 + acc[1][1] * cg[(9 + 2*c) * CS_STR];
        float sB = acc[0][2] * cg8[(2*c)     * CS_STR]
                 + acc[0][3] * cg8[(2*c + 1) * CS_STR]
                 + acc[1][2] * cg8[(8 + 2*c) * CS_STR]
                 + acc[1][3] * cg8[(9 + 2*c) * CS_STR];
        sA += __shfl_xor_sync(FULL, sA, 1);
        sA += __shfl_xor_sync(FULL, sA, 2);
        sB += __shfl_xor_sync(FULL, sB, 1);
        sB += __shfl_xor_sync(FULL, sB, 2);
        int rg  = __shfl_sync(FULL, r_, 2 * g);
        int rg8 = __shfl_sync(FULL, r_, 2 * g + 16);
        if (c == 0) {
            red1(out + rg,  sA);
            red1(out + rg8, sB);
        }
        __syncwarp();   // tail csm/praw reads done before next batch overwrites
    }
}

extern "C" void kernel_launch(void* const* d_in, const int* in_sizes, int n_in,
                              void* d_out, int out_size)
{
    const float* node_feats      = (const float*)d_in[0];
    const float* charges_induced = (const float*)d_in[2];
    const float* edge_feats      = (const float*)d_in[3];
    const float* edge_attrs      = (const float*)d_in[4];
    const float* mlp_w1          = (const float*)d_in[6];
    const float* mlp_w2          = (const float*)d_in[7];
    const float* mlp_w3          = (const float*)d_in[8];
    const float* mlp_w4          = (const float*)d_in[9];
    const float* W0              = (const float*)d_in[10];
    const float* W1              = (const float*)d_in[11];
    const int*   eidx            = (const int*)d_in[12];
    float* out = (float*)d_out;

    setup_kernel<<<(N_NODES + 7) / 8, 256>>>(node_feats, W0, W1,
                                             mlp_w1, mlp_w2, mlp_w3, mlp_w4, out);

    cudaFuncSetAttribute(edge_kernel, cudaFuncAttributeMaxDynamicSharedMemorySize, SMEM_BYTES);
    edge_kernel<<<GRID, 256, SMEM_BYTES>>>(
        edge_feats, edge_attrs, charges_induced, eidx, out);
}